// round 12
// baseline (speedup 1.0000x reference)
#include <cuda_runtime.h>
#include <math.h>

// ============================================================================
// Actor_att1 — R11: 8-lane groups, register-resident entity weights, ALL
// cross-lane exchange via shfl.sync (width=8). No smem h-buffers, no
// syncwarp in the hot loop. Lane role t owns hidden floats {4t..4t+3}
// (32-wide) and output floats {2t,2t+1} (16-wide). Packed f32x2 math.
// ============================================================================

typedef unsigned long long u64;
#define DINL __device__ __forceinline__

DINL u64 f2pack(float lo, float hi){u64 d;asm("mov.b64 %0,{%1,%2};":"=l"(d):"f"(lo),"f"(hi));return d;}
DINL u64 f2splat(float v){u64 d;asm("mov.b64 %0,{%1,%1};":"=l"(d):"f"(v));return d;}
DINL void f2unpack(u64 v,float&lo,float&hi){asm("mov.b64 {%0,%1},%2;":"=f"(lo),"=f"(hi):"l"(v));}
DINL u64 f2fma(u64 a,u64 b,u64 c){u64 d;asm("fma.rn.f32x2 %0,%1,%2,%3;":"=l"(d):"l"(a),"l"(b),"l"(c));return d;}
DINL u64 f2mul(u64 a,u64 b){u64 d;asm("mul.rn.f32x2 %0,%1,%2;":"=l"(d):"l"(a),"l"(b));return d;}
DINL u64 f2add(u64 a,u64 b){u64 d;asm("add.rn.f32x2 %0,%1,%2;":"=l"(d):"l"(a),"l"(b));return d;}
DINL u64 sh1(u64 v){return __shfl_xor_sync(0xffffffffu,v,1);}
DINL u64 sh2(u64 v){return __shfl_xor_sync(0xffffffffu,v,2);}
DINL u64 sh4(u64 v){return __shfl_xor_sync(0xffffffffu,v,4);}
DINL float sf1(float v){return __shfl_xor_sync(0xffffffffu,v,1);}
DINL float sf2(float v){return __shfl_xor_sync(0xffffffffu,v,2);}
DINL float sf4(float v){return __shfl_xor_sync(0xffffffffu,v,4);}
DINL u64 shg(u64 v,int src){return __shfl_sync(0xffffffffu,v,src,8);}  // group bcast

#define NT 384
#define ROWS 48
#define OBS 127

struct SW {
    float en_w1[4 * 32];  float en_b1[32];  float en_w2[32 * 16]; float en_b2[16];
    float oa_w1[5 * 32];  float oa_b1[32];  float oa_w2[32 * 16]; float oa_b2[16];
    float oa_g[16];       float oa_bln[16];
    float g_w1[3 * 32];   float g_b1[32];   float g_w2[32 * 16];  float g_b2[16];
    float g_g[16];        float g_bln[16];
    float m_w1[48 * 32];  float m_b1[32];   float m_w2[32 * 32];  float m_b2[32];
    float m_w3[32 * 2];   float m_b3[16];
};

DINL void cp_smem(float* dst, const float* __restrict__ src, int n, int tid) {
    for (int i = tid; i < n; i += NT) dst[i] = src[i];
}

DINL float red8(float v) { v += sf4(v); v += sf2(v); v += sf1(v); return v; }

__global__ void __launch_bounds__(NT, 1)
actor_kernel(const float* __restrict__ s_in,
             const float* __restrict__ en_w1, const float* __restrict__ en_b1,
             const float* __restrict__ en_w2, const float* __restrict__ en_b2,
             const float* __restrict__ oa_w1, const float* __restrict__ oa_b1,
             const float* __restrict__ oa_w2, const float* __restrict__ oa_b2,
             const float* __restrict__ oa_g,  const float* __restrict__ oa_bln,
             const float* __restrict__ g_w1,  const float* __restrict__ g_b1,
             const float* __restrict__ g_w2,  const float* __restrict__ g_b2,
             const float* __restrict__ g_g,   const float* __restrict__ g_bln,
             const float* __restrict__ m_w1,  const float* __restrict__ m_b1,
             const float* __restrict__ m_w2,  const float* __restrict__ m_b2,
             const float* __restrict__ m_w3,  const float* __restrict__ m_b3,
             float* __restrict__ out, int B)
{
    extern __shared__ __align__(16) float smem[];
    float* xs = smem;                              // ROWS*OBS floats
    SW* sw = reinterpret_cast<SW*>(xs + ROWS * OBS);

    const int tid = threadIdx.x;

    // ---- coalesced input staging (tail zero-filled) ----
    {
        const size_t base = (size_t)blockIdx.x * ROWS * OBS;
        const size_t tot = (size_t)B * OBS;
        const float4* src4 = reinterpret_cast<const float4*>(s_in + base);
        float4* dst4 = reinterpret_cast<float4*>(xs);
        const int full4 = ROWS * OBS / 4;          // 1524
        int n4 = full4;
        if (base + (size_t)full4 * 4 > tot) n4 = (int)((tot - base) / 4);
        for (int i = tid; i < n4; i += NT) dst4[i] = src4[i];
        if (n4 < full4) {
            float4 z = make_float4(0.f, 0.f, 0.f, 0.f);
            for (int i = n4 + tid; i < full4; i += NT) dst4[i] = z;
        }
    }

    cp_smem(sw->en_w1, en_w1, 4 * 32, tid);
    cp_smem(sw->en_b1, en_b1, 32, tid);
    cp_smem(sw->en_w2, en_w2, 32 * 16, tid);
    cp_smem(sw->en_b2, en_b2, 16, tid);
    cp_smem(sw->oa_w1, oa_w1, 5 * 32, tid);
    cp_smem(sw->oa_b1, oa_b1, 32, tid);
    cp_smem(sw->oa_w2, oa_w2, 32 * 16, tid);
    cp_smem(sw->oa_b2, oa_b2, 16, tid);
    cp_smem(sw->oa_g, oa_g, 16, tid);
    cp_smem(sw->oa_bln, oa_bln, 16, tid);
    cp_smem(sw->g_w1, g_w1, 3 * 32, tid);
    cp_smem(sw->g_b1, g_b1, 32, tid);
    cp_smem(sw->g_w2, g_w2, 32 * 16, tid);
    cp_smem(sw->g_b2, g_b2, 16, tid);
    cp_smem(sw->g_g, g_g, 16, tid);
    cp_smem(sw->g_bln, g_bln, 16, tid);
    cp_smem(sw->m_w1, m_w1, 48 * 32, tid);
    cp_smem(sw->m_b1, m_b1, 32, tid);
    cp_smem(sw->m_w2, m_w2, 32 * 32, tid);
    cp_smem(sw->m_b2, m_b2, 32, tid);
    cp_smem(sw->m_w3, m_w3, 32 * 2, tid);
    if (tid < 2) sw->m_b3[tid] = m_b3[tid];
    __syncthreads();

    const int warp = tid >> 5;
    const int lane = tid & 31;
    const int g = lane >> 3;           // group 0..3 within warp
    const int t = lane & 7;            // role 0..7
    const int rw = warp * 4 + g;       // CTA-local row 0..47
    const int row = blockIdx.x * ROWS + rw;

    const float* x = xs + rw * OBS;

    // ================= self encoder: 4 -> 32 -> 16 =================
    u64 sp;                            // my self_out pair {2t,2t+1}
    u64 msf;                           // same, saved for merge
    {
        u64 a0 = *reinterpret_cast<const u64*>(sw->en_b1 + 4 * t);
        u64 a1 = *reinterpret_cast<const u64*>(sw->en_b1 + 4 * t + 2);
#pragma unroll
        for (int k = 0; k < 4; k++) {
            u64 xv = f2splat(x[k]);
            const u64* wr = reinterpret_cast<const u64*>(sw->en_w1 + k * 32 + 4 * t);
            a0 = f2fma(xv, wr[0], a0);
            a1 = f2fma(xv, wr[1], a1);
        }
        float f0, f1, f2v, f3;
        f2unpack(a0, f0, f1); f2unpack(a1, f2v, f3);
        u64 p0 = f2pack(fmaxf(f0, 0.f), fmaxf(f1, 0.f));
        u64 p1 = f2pack(fmaxf(f2v, 0.f), fmaxf(f3, 0.f));

        u64 accA = *reinterpret_cast<const u64*>(sw->en_b2 + 2 * t);
        u64 accB = 0ull;
#pragma unroll
        for (int j = 0; j < 8; j++) {
            u64 q0 = shg(p0, j), q1 = shg(p1, j);
            float g0, g1, g2, g3;
            f2unpack(q0, g0, g1); f2unpack(q1, g2, g3);
            const float* wb = sw->en_w2 + (4 * j) * 16 + 2 * t;
            accA = f2fma(f2splat(g0), *reinterpret_cast<const u64*>(wb),      accA);
            accB = f2fma(f2splat(g1), *reinterpret_cast<const u64*>(wb + 16), accB);
            accA = f2fma(f2splat(g2), *reinterpret_cast<const u64*>(wb + 32), accA);
            accB = f2fma(f2splat(g3), *reinterpret_cast<const u64*>(wb + 48), accB);
        }
        u64 acc = f2add(accA, accB);
        float a, b; f2unpack(acc, a, b);
        a = fmaxf(a, 0.f); b = fmaxf(b, 0.f);
        sp = f2pack(a, b);
        msf = sp;
    }

    u64 mo, mf;   // other/food pairs for merge

    // ================= other-agent attention: 15 entities, K=5 =================
    {
        u64 w1h[5][2], w2h[32];
#pragma unroll
        for (int k = 0; k < 5; k++) {
            const u64* wr = reinterpret_cast<const u64*>(sw->oa_w1 + k * 32 + 4 * t);
            w1h[k][0] = wr[0]; w1h[k][1] = wr[1];
        }
        const u64 b1a = *reinterpret_cast<const u64*>(sw->oa_b1 + 4 * t);
        const u64 b1b = *reinterpret_cast<const u64*>(sw->oa_b1 + 4 * t + 2);
#pragma unroll
        for (int k = 0; k < 32; k++)
            w2h[k] = *reinterpret_cast<const u64*>(sw->oa_w2 + k * 16 + 2 * t);
        const u64 b2h = *reinterpret_cast<const u64*>(sw->oa_b2 + 2 * t);

        float mm = -__int_as_float(0x7f800000);
        float l = 0.f;
        u64 at = 0ull;

#pragma unroll 1
        for (int i = 0; i < 15; i++) {
            float in5[5];
            in5[0] = x[4 + 2 * i];
            in5[1] = x[5 + 2 * i];
            in5[2] = x[34 + 2 * i];
            in5[3] = x[35 + 2 * i];
            in5[4] = x[64 + i];

            u64 a0 = b1a, a1 = b1b;
#pragma unroll
            for (int k = 0; k < 5; k++) {
                u64 xv = f2splat(in5[k]);
                a0 = f2fma(xv, w1h[k][0], a0);
                a1 = f2fma(xv, w1h[k][1], a1);
            }
            float f0, f1, f2v, f3;
            f2unpack(a0, f0, f1); f2unpack(a1, f2v, f3);
            u64 p0 = f2pack(fmaxf(f0, 0.f), fmaxf(f1, 0.f));
            u64 p1 = f2pack(fmaxf(f2v, 0.f), fmaxf(f3, 0.f));

            u64 accA = b2h, accB = 0ull;
#pragma unroll
            for (int j = 0; j < 8; j++) {
                u64 q0 = shg(p0, j), q1 = shg(p1, j);
                float g0, g1, g2, g3;
                f2unpack(q0, g0, g1); f2unpack(q1, g2, g3);
                accA = f2fma(f2splat(g0), w2h[4 * j + 0], accA);
                accB = f2fma(f2splat(g1), w2h[4 * j + 1], accB);
                accA = f2fma(f2splat(g2), w2h[4 * j + 2], accA);
                accB = f2fma(f2splat(g3), w2h[4 * j + 3], accB);
            }
            u64 acc = f2add(accA, accB);
            float a, b; f2unpack(acc, a, b);
            a = fmaxf(a, 0.f); b = fmaxf(b, 0.f);
            u64 e = f2pack(a, b);

            u64 d2 = f2mul(sp, e);
            float dl, dh; f2unpack(d2, dl, dh);
            float s = red8(dl + dh) * 0.25f;

            float nm = fmaxf(mm, s);
            float corr = __expf(mm - nm);
            float pw   = __expf(s - nm);
            mm = nm;
            l = l * corr + pw;
            at = f2fma(f2splat(corr), at, f2mul(f2splat(pw), e));
        }

        float inv = __fdividef(1.f, l);
        float a, b; f2unpack(at, a, b);
        a *= inv; b *= inv;
        float mu = red8(a + b) * (1.f / 16.f);
        float ca = a - mu, cb = b - mu;
        float var = red8(ca * ca + cb * cb) * (1.f / 16.f);
        float rs = rsqrtf(var + 1e-5f);
        float o0 = fmaxf(ca * rs * sw->oa_g[2 * t]     + sw->oa_bln[2 * t],     0.f);
        float o1 = fmaxf(cb * rs * sw->oa_g[2 * t + 1] + sw->oa_bln[2 * t + 1], 0.f);
        mo = f2pack(o0, o1);
    }

    // ================= food attention: 16 entities, K=3 =================
    {
        u64 w1h[3][2], w2h[32];
#pragma unroll
        for (int k = 0; k < 3; k++) {
            const u64* wr = reinterpret_cast<const u64*>(sw->g_w1 + k * 32 + 4 * t);
            w1h[k][0] = wr[0]; w1h[k][1] = wr[1];
        }
        const u64 b1a = *reinterpret_cast<const u64*>(sw->g_b1 + 4 * t);
        const u64 b1b = *reinterpret_cast<const u64*>(sw->g_b1 + 4 * t + 2);
#pragma unroll
        for (int k = 0; k < 32; k++)
            w2h[k] = *reinterpret_cast<const u64*>(sw->g_w2 + k * 16 + 2 * t);
        const u64 b2h = *reinterpret_cast<const u64*>(sw->g_b2 + 2 * t);

        float mm = -__int_as_float(0x7f800000);
        float l = 0.f;
        u64 at = 0ull;

#pragma unroll 1
        for (int i = 0; i < 16; i++) {
            float in3[3];
            in3[0] = x[79 + 3 * i];
            in3[1] = x[80 + 3 * i];
            in3[2] = x[81 + 3 * i];

            u64 a0 = b1a, a1 = b1b;
#pragma unroll
            for (int k = 0; k < 3; k++) {
                u64 xv = f2splat(in3[k]);
                a0 = f2fma(xv, w1h[k][0], a0);
                a1 = f2fma(xv, w1h[k][1], a1);
            }
            float f0, f1, f2v, f3;
            f2unpack(a0, f0, f1); f2unpack(a1, f2v, f3);
            u64 p0 = f2pack(fmaxf(f0, 0.f), fmaxf(f1, 0.f));
            u64 p1 = f2pack(fmaxf(f2v, 0.f), fmaxf(f3, 0.f));

            u64 accA = b2h, accB = 0ull;
#pragma unroll
            for (int j = 0; j < 8; j++) {
                u64 q0 = shg(p0, j), q1 = shg(p1, j);
                float g0, g1, g2, g3;
                f2unpack(q0, g0, g1); f2unpack(q1, g2, g3);
                accA = f2fma(f2splat(g0), w2h[4 * j + 0], accA);
                accB = f2fma(f2splat(g1), w2h[4 * j + 1], accB);
                accA = f2fma(f2splat(g2), w2h[4 * j + 2], accA);
                accB = f2fma(f2splat(g3), w2h[4 * j + 3], accB);
            }
            u64 acc = f2add(accA, accB);
            float a, b; f2unpack(acc, a, b);
            a = fmaxf(a, 0.f); b = fmaxf(b, 0.f);
            u64 e = f2pack(a, b);

            u64 d2 = f2mul(sp, e);
            float dl, dh; f2unpack(d2, dl, dh);
            float s = red8(dl + dh) * 0.25f;

            float nm = fmaxf(mm, s);
            float corr = __expf(mm - nm);
            float pw   = __expf(s - nm);
            mm = nm;
            l = l * corr + pw;
            at = f2fma(f2splat(corr), at, f2mul(f2splat(pw), e));
        }

        float inv = __fdividef(1.f, l);
        float a, b; f2unpack(at, a, b);
        a *= inv; b *= inv;
        float mu = red8(a + b) * (1.f / 16.f);
        float ca = a - mu, cb = b - mu;
        float var = red8(ca * ca + cb * cb) * (1.f / 16.f);
        float rs = rsqrtf(var + 1e-5f);
        float o0 = fmaxf(ca * rs * sw->g_g[2 * t]     + sw->g_bln[2 * t],     0.f);
        float o1 = fmaxf(cb * rs * sw->g_g[2 * t + 1] + sw->g_bln[2 * t + 1], 0.f);
        mf = f2pack(o0, o1);
    }

    // ================= merge head: 48 -> 32 -> 32 -> 2 =================
    // Merged vector: cols {2j,2j+1}=self(lane j), {16+..}=food, {32+..}=other.
    u64 hp0, hp1;  // h1 packed: my 4 floats {4t..4t+3}
    {
        u64 a0 = *reinterpret_cast<const u64*>(sw->m_b1 + 4 * t);
        u64 a1 = *reinterpret_cast<const u64*>(sw->m_b1 + 4 * t + 2);
#pragma unroll
        for (int j = 0; j < 8; j++) {
            u64 qs = shg(msf, j), qf = shg(mf, j), qo = shg(mo, j);
            float s0, s1, f0, f1, o0, o1;
            f2unpack(qs, s0, s1); f2unpack(qf, f0, f1); f2unpack(qo, o0, o1);
            const float* w;
            w = sw->m_w1 + (2 * j) * 32 + 4 * t;
            a0 = f2fma(f2splat(s0), *reinterpret_cast<const u64*>(w), a0);
            a1 = f2fma(f2splat(s0), *reinterpret_cast<const u64*>(w + 2), a1);
            w += 32;
            a0 = f2fma(f2splat(s1), *reinterpret_cast<const u64*>(w), a0);
            a1 = f2fma(f2splat(s1), *reinterpret_cast<const u64*>(w + 2), a1);
            w = sw->m_w1 + (16 + 2 * j) * 32 + 4 * t;
            a0 = f2fma(f2splat(f0), *reinterpret_cast<const u64*>(w), a0);
            a1 = f2fma(f2splat(f0), *reinterpret_cast<const u64*>(w + 2), a1);
            w += 32;
            a0 = f2fma(f2splat(f1), *reinterpret_cast<const u64*>(w), a0);
            a1 = f2fma(f2splat(f1), *reinterpret_cast<const u64*>(w + 2), a1);
            w = sw->m_w1 + (32 + 2 * j) * 32 + 4 * t;
            a0 = f2fma(f2splat(o0), *reinterpret_cast<const u64*>(w), a0);
            a1 = f2fma(f2splat(o0), *reinterpret_cast<const u64*>(w + 2), a1);
            w += 32;
            a0 = f2fma(f2splat(o1), *reinterpret_cast<const u64*>(w), a0);
            a1 = f2fma(f2splat(o1), *reinterpret_cast<const u64*>(w + 2), a1);
        }
        float f0, f1, f2v, f3;
        f2unpack(a0, f0, f1); f2unpack(a1, f2v, f3);
        hp0 = f2pack(fmaxf(f0, 0.01f * f0), fmaxf(f1, 0.01f * f1));
        hp1 = f2pack(fmaxf(f2v, 0.01f * f2v), fmaxf(f3, 0.01f * f3));
    }

    float h2[4];
    {
        u64 a0 = *reinterpret_cast<const u64*>(sw->m_b2 + 4 * t);
        u64 a1 = *reinterpret_cast<const u64*>(sw->m_b2 + 4 * t + 2);
#pragma unroll
        for (int j = 0; j < 8; j++) {
            u64 q0 = shg(hp0, j), q1 = shg(hp1, j);
            float g0, g1, g2, g3;
            f2unpack(q0, g0, g1); f2unpack(q1, g2, g3);
            const float* wb = sw->m_w2 + (4 * j) * 32 + 4 * t;
            a0 = f2fma(f2splat(g0), *reinterpret_cast<const u64*>(wb), a0);
            a1 = f2fma(f2splat(g0), *reinterpret_cast<const u64*>(wb + 2), a1);
            a0 = f2fma(f2splat(g1), *reinterpret_cast<const u64*>(wb + 32), a0);
            a1 = f2fma(f2splat(g1), *reinterpret_cast<const u64*>(wb + 34), a1);
            a0 = f2fma(f2splat(g2), *reinterpret_cast<const u64*>(wb + 64), a0);
            a1 = f2fma(f2splat(g2), *reinterpret_cast<const u64*>(wb + 66), a1);
            a0 = f2fma(f2splat(g3), *reinterpret_cast<const u64*>(wb + 96), a0);
            a1 = f2fma(f2splat(g3), *reinterpret_cast<const u64*>(wb + 98), a1);
        }
        float f0, f1, f2v, f3;
        f2unpack(a0, f0, f1); f2unpack(a1, f2v, f3);
        h2[0] = fmaxf(f0, 0.01f * f0);
        h2[1] = fmaxf(f1, 0.01f * f1);
        h2[2] = fmaxf(f2v, 0.01f * f2v);
        h2[3] = fmaxf(f3, 0.01f * f3);
    }

    // m3: 32 -> 2, k-split over my 4 h2 dims {4t..4t+3}, 8-lane reduce
    {
        u64 acc = 0ull;
#pragma unroll
        for (int j = 0; j < 4; j++) {
            const int k = 4 * t + j;
            acc = f2fma(f2splat(h2[j]),
                        *reinterpret_cast<const u64*>(sw->m_w3 + 2 * k), acc);
        }
        acc = f2add(acc, sh4(acc));
        acc = f2add(acc, sh2(acc));
        acc = f2add(acc, sh1(acc));
        if (t == 0 && row < B) {
            acc = f2add(acc, *reinterpret_cast<const u64*>(sw->m_b3));
            float a, b; f2unpack(acc, a, b);
            reinterpret_cast<float2*>(out)[row] = make_float2(tanhf(a), tanhf(b));
        }
    }
}

extern "C" void kernel_launch(void* const* d_in, const int* in_sizes, int n_in,
                              void* d_out, int out_size) {
    const float* s_in = (const float*)d_in[0];
    const int B = in_sizes[0] / OBS;
    const size_t shbytes = (size_t)ROWS * OBS * sizeof(float) + sizeof(SW);
    cudaFuncSetAttribute(actor_kernel,
                         cudaFuncAttributeMaxDynamicSharedMemorySize, (int)shbytes);
    dim3 grid((B + ROWS - 1) / ROWS), block(NT);
    actor_kernel<<<grid, block, shbytes>>>(
        s_in,
        (const float*)d_in[1],  (const float*)d_in[2],
        (const float*)d_in[3],  (const float*)d_in[4],
        (const float*)d_in[5],  (const float*)d_in[6],
        (const float*)d_in[7],  (const float*)d_in[8],
        (const float*)d_in[9],  (const float*)d_in[10],
        (const float*)d_in[11], (const float*)d_in[12],
        (const float*)d_in[13], (const float*)d_in[14],
        (const float*)d_in[15], (const float*)d_in[16],
        (const float*)d_in[17], (const float*)d_in[18],
        (const float*)d_in[19], (const float*)d_in[20],
        (const float*)d_in[21], (const float*)d_in[22],
        (float*)d_out, B);
}

// round 13
// speedup vs baseline: 4.4189x; 4.4189x over previous
#include <cuda_runtime.h>
#include <stdint.h>
#include <math.h>

// ============================================================================
// Actor_att1 — R12: tf32 mma.sync tensor-core rewrite.
// Warp = 32 rows (items). Lane l: q = l/4 (item-group), t = l%4 (role).
// Items handled per lane: {16T + q + 8b : T,b in {0,1}}.
// Layer1 (K<=5) in exact fp32 FMA2 producing mma A-fragments natively
//   (lane owns hidden dims t+4j, j=0..7; items packed as f32x2 pairs).
// Layer2 (32->16) = mma.sync.m16n8k8 tf32, B-fragments (weights) in regs.
// Softmax/LN fp32 with quad shfl reduce. Merge head via mma with smem
// round-trip (reusing this warp's input rows; warp-private).
// ============================================================================

typedef unsigned long long u64;
#define DINL __device__ __forceinline__

DINL u64 f2pack(float lo, float hi){u64 d;asm("mov.b64 %0,{%1,%2};":"=l"(d):"f"(lo),"f"(hi));return d;}
DINL u64 f2splat(float v){u64 d;asm("mov.b64 %0,{%1,%1};":"=l"(d):"f"(v));return d;}
DINL void f2unpack(u64 v,float&lo,float&hi){asm("mov.b64 {%0,%1},%2;":"=f"(lo),"=f"(hi):"l"(v));}
DINL u64 f2fma(u64 a,u64 b,u64 c){u64 d;asm("fma.rn.f32x2 %0,%1,%2,%3;":"=l"(d):"l"(a),"l"(b),"l"(c));return d;}
DINL u64 f2mul(u64 a,u64 b){u64 d;asm("mul.rn.f32x2 %0,%1,%2;":"=l"(d):"l"(a),"l"(b));return d;}
DINL u64 f2add(u64 a,u64 b){u64 d;asm("add.rn.f32x2 %0,%1,%2;":"=l"(d):"l"(a),"l"(b));return d;}
DINL u64 sh1(u64 v){return __shfl_xor_sync(0xffffffffu,v,1);}
DINL u64 sh2(u64 v){return __shfl_xor_sync(0xffffffffu,v,2);}
DINL float sf1(float v){return __shfl_xor_sync(0xffffffffu,v,1);}
DINL float sf2(float v){return __shfl_xor_sync(0xffffffffu,v,2);}

DINL uint32_t tf32(float x){uint32_t u;asm("cvt.rna.tf32.f32 %0,%1;":"=r"(u):"f"(x));return u;}

DINL void mma8(float&c0,float&c1,float&c2,float&c3,
               uint32_t a0,uint32_t a1,uint32_t a2,uint32_t a3,
               uint32_t b0,uint32_t b1){
    asm("mma.sync.aligned.m16n8k8.row.col.f32.tf32.tf32.f32 "
        "{%0,%1,%2,%3},{%4,%5,%6,%7},{%8,%9},{%0,%1,%2,%3};"
        : "+f"(c0),"+f"(c1),"+f"(c2),"+f"(c3)
        : "r"(a0),"r"(a1),"r"(a2),"r"(a3),"r"(b0),"r"(b1));
}

DINL float lrelu(float x){ return fmaxf(x, 0.01f * x); }

#define NT 256
#define ROWS 256
#define OBS 127

struct SW {
    float en_w1[4 * 32];  float en_b1[32];  float en_w2[32 * 16]; float en_b2[16];
    float oa_w1[5 * 32];  float oa_b1[32];  float oa_w2[32 * 16]; float oa_b2[16];
    float oa_g[16];       float oa_bln[16];
    float g_w1[3 * 32];   float g_b1[32];   float g_w2[32 * 16];  float g_b2[16];
    float g_g[16];        float g_bln[16];
    float m_w1[48 * 32];  float m_b1[32];   float m_w2[32 * 32];  float m_b2[32];
    float m_w3[32 * 2];   float m_b3[16];
};

DINL void cp_smem(float* dst, const float* __restrict__ src, int n, int tid) {
    for (int i = tid; i < n; i += NT) dst[i] = src[i];
}

// Shared encoder: fp32 layer1 (K->32, dims t+4j) + tf32 mma layer2 (32->16).
// in[T][b][k]; Bf = layer2 B-fragments; output ep[T][N][b] relu'd pairs
// (floats {8N+2t, 8N+2t+1} of item 16T+q+8b).
template<int K>
DINL void enc(const float (&in)[2][2][K], const float (&w1v)[K * 8],
              const float (&b1v)[8], const uint32_t (&Bf)[2][4][2],
              const float (&b2v)[2][2], u64 (&ep)[2][2][2]) {
    uint32_t Alo[2][8], Ahi[2][8];
#pragma unroll
    for (int T = 0; T < 2; T++) {
        u64 acc[8];
#pragma unroll
        for (int j = 0; j < 8; j++) acc[j] = f2splat(b1v[j]);
#pragma unroll
        for (int k = 0; k < K; k++) {
            u64 xp = f2pack(in[T][0][k], in[T][1][k]);
#pragma unroll
            for (int j = 0; j < 8; j++)
                acc[j] = f2fma(xp, f2splat(w1v[k * 8 + j]), acc[j]);
        }
#pragma unroll
        for (int j = 0; j < 8; j++) {
            float a, b; f2unpack(acc[j], a, b);
            Alo[T][j] = tf32(fmaxf(a, 0.f));
            Ahi[T][j] = tf32(fmaxf(b, 0.f));
        }
    }
#pragma unroll
    for (int T = 0; T < 2; T++)
#pragma unroll
        for (int N = 0; N < 2; N++) {
            float c0 = b2v[N][0], c1 = b2v[N][1], c2 = b2v[N][0], c3 = b2v[N][1];
#pragma unroll
            for (int s = 0; s < 4; s++)
                mma8(c0, c1, c2, c3,
                     Alo[T][2 * s], Ahi[T][2 * s], Alo[T][2 * s + 1], Ahi[T][2 * s + 1],
                     Bf[N][s][0], Bf[N][s][1]);
            ep[T][N][0] = f2pack(fmaxf(c0, 0.f), fmaxf(c1, 0.f));
            ep[T][N][1] = f2pack(fmaxf(c2, 0.f), fmaxf(c3, 0.f));
        }
}

__global__ void __launch_bounds__(NT, 1)
actor_kernel(const float* __restrict__ s_in,
             const float* __restrict__ en_w1, const float* __restrict__ en_b1,
             const float* __restrict__ en_w2, const float* __restrict__ en_b2,
             const float* __restrict__ oa_w1, const float* __restrict__ oa_b1,
             const float* __restrict__ oa_w2, const float* __restrict__ oa_b2,
             const float* __restrict__ oa_g,  const float* __restrict__ oa_bln,
             const float* __restrict__ g_w1,  const float* __restrict__ g_b1,
             const float* __restrict__ g_w2,  const float* __restrict__ g_b2,
             const float* __restrict__ g_g,   const float* __restrict__ g_bln,
             const float* __restrict__ m_w1,  const float* __restrict__ m_b1,
             const float* __restrict__ m_w2,  const float* __restrict__ m_b2,
             const float* __restrict__ m_w3,  const float* __restrict__ m_b3,
             float* __restrict__ out, int B)
{
    extern __shared__ __align__(16) float smem[];
    float* xs = smem;                              // ROWS*OBS floats
    SW* sw = reinterpret_cast<SW*>(xs + ROWS * OBS);

    const int tid = threadIdx.x;

    // ---- coalesced input staging (tail zero-filled) ----
    {
        const size_t base = (size_t)blockIdx.x * ROWS * OBS;
        const size_t tot = (size_t)B * OBS;
        const float4* src4 = reinterpret_cast<const float4*>(s_in + base);
        float4* dst4 = reinterpret_cast<float4*>(xs);
        const int full4 = ROWS * OBS / 4;
        int n4 = full4;
        if (base + (size_t)full4 * 4 > tot) n4 = (int)((tot - base) / 4);
        for (int i = tid; i < n4; i += NT) dst4[i] = src4[i];
        if (n4 < full4) {
            float4 z = make_float4(0.f, 0.f, 0.f, 0.f);
            for (int i = n4 + tid; i < full4; i += NT) dst4[i] = z;
        }
    }

    cp_smem(sw->en_w1, en_w1, 4 * 32, tid);
    cp_smem(sw->en_b1, en_b1, 32, tid);
    cp_smem(sw->en_w2, en_w2, 32 * 16, tid);
    cp_smem(sw->en_b2, en_b2, 16, tid);
    cp_smem(sw->oa_w1, oa_w1, 5 * 32, tid);
    cp_smem(sw->oa_b1, oa_b1, 32, tid);
    cp_smem(sw->oa_w2, oa_w2, 32 * 16, tid);
    cp_smem(sw->oa_b2, oa_b2, 16, tid);
    cp_smem(sw->oa_g, oa_g, 16, tid);
    cp_smem(sw->oa_bln, oa_bln, 16, tid);
    cp_smem(sw->g_w1, g_w1, 3 * 32, tid);
    cp_smem(sw->g_b1, g_b1, 32, tid);
    cp_smem(sw->g_w2, g_w2, 32 * 16, tid);
    cp_smem(sw->g_b2, g_b2, 16, tid);
    cp_smem(sw->g_g, g_g, 16, tid);
    cp_smem(sw->g_bln, g_bln, 16, tid);
    cp_smem(sw->m_w1, m_w1, 48 * 32, tid);
    cp_smem(sw->m_b1, m_b1, 32, tid);
    cp_smem(sw->m_w2, m_w2, 32 * 32, tid);
    cp_smem(sw->m_b2, m_b2, 32, tid);
    cp_smem(sw->m_w3, m_w3, 32 * 2, tid);
    if (tid < 2) sw->m_b3[tid] = m_b3[tid];
    __syncthreads();

    const int warp = tid >> 5;
    const int lane = tid & 31;
    const int q = lane >> 2;          // item-group 0..7
    const int t = lane & 3;           // role 0..3
    const int rbase = warp * 32;      // CTA-local row base for this warp

    const float* xr[2][2];
#pragma unroll
    for (int T = 0; T < 2; T++)
#pragma unroll
        for (int b = 0; b < 2; b++)
            xr[T][b] = xs + (rbase + 16 * T + q + 8 * b) * OBS;

    // ================= self encoder: 4 -> 32 -> 16 =================
    u64 spv[2][2][2];
    {
        float w1v[32], b1v[8];
#pragma unroll
        for (int k = 0; k < 4; k++)
#pragma unroll
            for (int j = 0; j < 8; j++) w1v[k * 8 + j] = sw->en_w1[k * 32 + t + 4 * j];
#pragma unroll
        for (int j = 0; j < 8; j++) b1v[j] = sw->en_b1[t + 4 * j];
        uint32_t Bf[2][4][2];
        float b2v[2][2];
#pragma unroll
        for (int N = 0; N < 2; N++) {
#pragma unroll
            for (int s = 0; s < 4; s++) {
                Bf[N][s][0] = tf32(sw->en_w2[(8 * s + t) * 16 + 8 * N + q]);
                Bf[N][s][1] = tf32(sw->en_w2[(8 * s + t + 4) * 16 + 8 * N + q]);
            }
            b2v[N][0] = sw->en_b2[8 * N + 2 * t];
            b2v[N][1] = sw->en_b2[8 * N + 2 * t + 1];
        }
        float in[2][2][4];
#pragma unroll
        for (int T = 0; T < 2; T++)
#pragma unroll
            for (int b = 0; b < 2; b++)
#pragma unroll
                for (int k = 0; k < 4; k++) in[T][b][k] = xr[T][b][k];
        enc<4>(in, w1v, b1v, Bf, b2v, spv);
    }

    u64 ov[2][2][2], fv[2][2][2];

    // ================= other-agent attention: 15 entities, K=5 =================
    {
        float w1v[40], b1v[8];
#pragma unroll
        for (int k = 0; k < 5; k++)
#pragma unroll
            for (int j = 0; j < 8; j++) w1v[k * 8 + j] = sw->oa_w1[k * 32 + t + 4 * j];
#pragma unroll
        for (int j = 0; j < 8; j++) b1v[j] = sw->oa_b1[t + 4 * j];
        uint32_t Bf[2][4][2];
        float b2v[2][2];
#pragma unroll
        for (int N = 0; N < 2; N++) {
#pragma unroll
            for (int s = 0; s < 4; s++) {
                Bf[N][s][0] = tf32(sw->oa_w2[(8 * s + t) * 16 + 8 * N + q]);
                Bf[N][s][1] = tf32(sw->oa_w2[(8 * s + t + 4) * 16 + 8 * N + q]);
            }
            b2v[N][0] = sw->oa_b2[8 * N + 2 * t];
            b2v[N][1] = sw->oa_b2[8 * N + 2 * t + 1];
        }

        float mm[2][2], ll[2][2];
        u64 at[2][2][2];
#pragma unroll
        for (int T = 0; T < 2; T++)
#pragma unroll
            for (int b = 0; b < 2; b++) {
                mm[T][b] = -__int_as_float(0x7f800000);
                ll[T][b] = 0.f;
                at[T][0][b] = 0ull; at[T][1][b] = 0ull;
            }

#pragma unroll 1
        for (int i = 0; i < 15; i++) {
            float in[2][2][5];
#pragma unroll
            for (int T = 0; T < 2; T++)
#pragma unroll
                for (int b = 0; b < 2; b++) {
                    const float* xp = xr[T][b];
                    in[T][b][0] = xp[4 + 2 * i];
                    in[T][b][1] = xp[5 + 2 * i];
                    in[T][b][2] = xp[34 + 2 * i];
                    in[T][b][3] = xp[35 + 2 * i];
                    in[T][b][4] = xp[64 + i];
                }
            u64 ep[2][2][2];
            enc<5>(in, w1v, b1v, Bf, b2v, ep);

#pragma unroll
            for (int T = 0; T < 2; T++)
#pragma unroll
                for (int b = 0; b < 2; b++) {
                    u64 d = f2mul(spv[T][0][b], ep[T][0][b]);
                    d = f2fma(spv[T][1][b], ep[T][1][b], d);
                    float lo, hi; f2unpack(d, lo, hi);
                    float p = lo + hi;
                    p += sf1(p); p += sf2(p);
                    float s = p * 0.25f;
                    float nm = fmaxf(mm[T][b], s);
                    float corr = __expf(mm[T][b] - nm);
                    float pw   = __expf(s - nm);
                    mm[T][b] = nm;
                    ll[T][b] = ll[T][b] * corr + pw;
                    u64 cs = f2splat(corr), ps = f2splat(pw);
                    at[T][0][b] = f2fma(cs, at[T][0][b], f2mul(ps, ep[T][0][b]));
                    at[T][1][b] = f2fma(cs, at[T][1][b], f2mul(ps, ep[T][1][b]));
                }
        }

        float g4[4], bt4[4];
        g4[0] = sw->oa_g[2 * t];     g4[1] = sw->oa_g[2 * t + 1];
        g4[2] = sw->oa_g[8 + 2 * t]; g4[3] = sw->oa_g[8 + 2 * t + 1];
        bt4[0] = sw->oa_bln[2 * t];     bt4[1] = sw->oa_bln[2 * t + 1];
        bt4[2] = sw->oa_bln[8 + 2 * t]; bt4[3] = sw->oa_bln[8 + 2 * t + 1];
#pragma unroll
        for (int T = 0; T < 2; T++)
#pragma unroll
            for (int b = 0; b < 2; b++) {
                float inv = __fdividef(1.f, ll[T][b]);
                float v0, v1, v2, v3;
                f2unpack(at[T][0][b], v0, v1);
                f2unpack(at[T][1][b], v2, v3);
                v0 *= inv; v1 *= inv; v2 *= inv; v3 *= inv;
                float sm = v0 + v1 + v2 + v3;
                sm += sf1(sm); sm += sf2(sm);
                float mu = sm * (1.f / 16.f);
                float c0 = v0 - mu, c1 = v1 - mu, c2 = v2 - mu, c3 = v3 - mu;
                float vr = c0 * c0 + c1 * c1 + c2 * c2 + c3 * c3;
                vr += sf1(vr); vr += sf2(vr);
                float rs = rsqrtf(vr * (1.f / 16.f) + 1e-5f);
                ov[T][0][b] = f2pack(fmaxf(c0 * rs * g4[0] + bt4[0], 0.f),
                                     fmaxf(c1 * rs * g4[1] + bt4[1], 0.f));
                ov[T][1][b] = f2pack(fmaxf(c2 * rs * g4[2] + bt4[2], 0.f),
                                     fmaxf(c3 * rs * g4[3] + bt4[3], 0.f));
            }
    }

    // ================= food attention: 16 entities, K=3 =================
    {
        float w1v[24], b1v[8];
#pragma unroll
        for (int k = 0; k < 3; k++)
#pragma unroll
            for (int j = 0; j < 8; j++) w1v[k * 8 + j] = sw->g_w1[k * 32 + t + 4 * j];
#pragma unroll
        for (int j = 0; j < 8; j++) b1v[j] = sw->g_b1[t + 4 * j];
        uint32_t Bf[2][4][2];
        float b2v[2][2];
#pragma unroll
        for (int N = 0; N < 2; N++) {
#pragma unroll
            for (int s = 0; s < 4; s++) {
                Bf[N][s][0] = tf32(sw->g_w2[(8 * s + t) * 16 + 8 * N + q]);
                Bf[N][s][1] = tf32(sw->g_w2[(8 * s + t + 4) * 16 + 8 * N + q]);
            }
            b2v[N][0] = sw->g_b2[8 * N + 2 * t];
            b2v[N][1] = sw->g_b2[8 * N + 2 * t + 1];
        }

        float mm[2][2], ll[2][2];
        u64 at[2][2][2];
#pragma unroll
        for (int T = 0; T < 2; T++)
#pragma unroll
            for (int b = 0; b < 2; b++) {
                mm[T][b] = -__int_as_float(0x7f800000);
                ll[T][b] = 0.f;
                at[T][0][b] = 0ull; at[T][1][b] = 0ull;
            }

#pragma unroll 1
        for (int i = 0; i < 16; i++) {
            float in[2][2][3];
#pragma unroll
            for (int T = 0; T < 2; T++)
#pragma unroll
                for (int b = 0; b < 2; b++) {
                    const float* xp = xr[T][b];
                    in[T][b][0] = xp[79 + 3 * i];
                    in[T][b][1] = xp[80 + 3 * i];
                    in[T][b][2] = xp[81 + 3 * i];
                }
            u64 ep[2][2][2];
            enc<3>(in, w1v, b1v, Bf, b2v, ep);

#pragma unroll
            for (int T = 0; T < 2; T++)
#pragma unroll
                for (int b = 0; b < 2; b++) {
                    u64 d = f2mul(spv[T][0][b], ep[T][0][b]);
                    d = f2fma(spv[T][1][b], ep[T][1][b], d);
                    float lo, hi; f2unpack(d, lo, hi);
                    float p = lo + hi;
                    p += sf1(p); p += sf2(p);
                    float s = p * 0.25f;
                    float nm = fmaxf(mm[T][b], s);
                    float corr = __expf(mm[T][b] - nm);
                    float pw   = __expf(s - nm);
                    mm[T][b] = nm;
                    ll[T][b] = ll[T][b] * corr + pw;
                    u64 cs = f2splat(corr), ps = f2splat(pw);
                    at[T][0][b] = f2fma(cs, at[T][0][b], f2mul(ps, ep[T][0][b]));
                    at[T][1][b] = f2fma(cs, at[T][1][b], f2mul(ps, ep[T][1][b]));
                }
        }

        float g4[4], bt4[4];
        g4[0] = sw->g_g[2 * t];     g4[1] = sw->g_g[2 * t + 1];
        g4[2] = sw->g_g[8 + 2 * t]; g4[3] = sw->g_g[8 + 2 * t + 1];
        bt4[0] = sw->g_bln[2 * t];     bt4[1] = sw->g_bln[2 * t + 1];
        bt4[2] = sw->g_bln[8 + 2 * t]; bt4[3] = sw->g_bln[8 + 2 * t + 1];
#pragma unroll
        for (int T = 0; T < 2; T++)
#pragma unroll
            for (int b = 0; b < 2; b++) {
                float inv = __fdividef(1.f, ll[T][b]);
                float v0, v1, v2, v3;
                f2unpack(at[T][0][b], v0, v1);
                f2unpack(at[T][1][b], v2, v3);
                v0 *= inv; v1 *= inv; v2 *= inv; v3 *= inv;
                float sm = v0 + v1 + v2 + v3;
                sm += sf1(sm); sm += sf2(sm);
                float mu = sm * (1.f / 16.f);
                float c0 = v0 - mu, c1 = v1 - mu, c2 = v2 - mu, c3 = v3 - mu;
                float vr = c0 * c0 + c1 * c1 + c2 * c2 + c3 * c3;
                vr += sf1(vr); vr += sf2(vr);
                float rs = rsqrtf(vr * (1.f / 16.f) + 1e-5f);
                fv[T][0][b] = f2pack(fmaxf(c0 * rs * g4[0] + bt4[0], 0.f),
                                     fmaxf(c1 * rs * g4[1] + bt4[1], 0.f));
                fv[T][1][b] = f2pack(fmaxf(c2 * rs * g4[2] + bt4[2], 0.f),
                                     fmaxf(c3 * rs * g4[3] + bt4[3], 0.f));
            }
    }

    // ============== merged vector -> smem (reuse this warp's x rows) ==============
    // merged[48]: cols 0..15 self, 16..31 food, 32..47 other.
#pragma unroll
    for (int T = 0; T < 2; T++)
#pragma unroll
        for (int b = 0; b < 2; b++) {
            float* M = xs + (rbase + 16 * T + q + 8 * b) * OBS;
#pragma unroll
            for (int N = 0; N < 2; N++) {
                float a, c;
                f2unpack(spv[T][N][b], a, c);
                M[8 * N + 2 * t] = a; M[8 * N + 2 * t + 1] = c;
                f2unpack(fv[T][N][b], a, c);
                M[16 + 8 * N + 2 * t] = a; M[16 + 8 * N + 2 * t + 1] = c;
                f2unpack(ov[T][N][b], a, c);
                M[32 + 8 * N + 2 * t] = a; M[32 + 8 * N + 2 * t + 1] = c;
            }
        }
    __syncwarp();

    // ============== m1: 48 -> 32 via mma (K=48, 6 k-steps) ==============
    {
        uint32_t Am[2][6][4];
#pragma unroll
        for (int T = 0; T < 2; T++) {
            const float* r0 = xs + (rbase + 16 * T + q) * OBS;
            const float* r1 = r0 + 8 * OBS;
#pragma unroll
            for (int s = 0; s < 6; s++) {
                Am[T][s][0] = tf32(r0[8 * s + t]);
                Am[T][s][1] = tf32(r1[8 * s + t]);
                Am[T][s][2] = tf32(r0[8 * s + t + 4]);
                Am[T][s][3] = tf32(r1[8 * s + t + 4]);
            }
        }
#pragma unroll
        for (int N = 0; N < 4; N++) {
            uint32_t Bm[6][2];
#pragma unroll
            for (int s = 0; s < 6; s++) {
                Bm[s][0] = tf32(sw->m_w1[(8 * s + t) * 32 + 8 * N + q]);
                Bm[s][1] = tf32(sw->m_w1[(8 * s + t + 4) * 32 + 8 * N + q]);
            }
            float bb0 = sw->m_b1[8 * N + 2 * t], bb1 = sw->m_b1[8 * N + 2 * t + 1];
#pragma unroll
            for (int T = 0; T < 2; T++) {
                float c0 = bb0, c1 = bb1, c2 = bb0, c3 = bb1;
#pragma unroll
                for (int s = 0; s < 6; s++)
                    mma8(c0, c1, c2, c3,
                         Am[T][s][0], Am[T][s][1], Am[T][s][2], Am[T][s][3],
                         Bm[s][0], Bm[s][1]);
                float* r0 = xs + (rbase + 16 * T + q) * OBS;
                float* r1 = r0 + 8 * OBS;
                r0[64 + 8 * N + 2 * t]     = lrelu(c0);
                r0[64 + 8 * N + 2 * t + 1] = lrelu(c1);
                r1[64 + 8 * N + 2 * t]     = lrelu(c2);
                r1[64 + 8 * N + 2 * t + 1] = lrelu(c3);
            }
        }
    }
    __syncwarp();

    // ============== m2: 32 -> 32 via mma (K=32, 4 k-steps) ==============
    u64 h2p[2][4][2];
    {
        uint32_t Am[2][4][4];
#pragma unroll
        for (int T = 0; T < 2; T++) {
            const float* r0 = xs + (rbase + 16 * T + q) * OBS;
            const float* r1 = r0 + 8 * OBS;
#pragma unroll
            for (int s = 0; s < 4; s++) {
                Am[T][s][0] = tf32(r0[64 + 8 * s + t]);
                Am[T][s][1] = tf32(r1[64 + 8 * s + t]);
                Am[T][s][2] = tf32(r0[64 + 8 * s + t + 4]);
                Am[T][s][3] = tf32(r1[64 + 8 * s + t + 4]);
            }
        }
#pragma unroll
        for (int N = 0; N < 4; N++) {
            uint32_t Bm[4][2];
#pragma unroll
            for (int s = 0; s < 4; s++) {
                Bm[s][0] = tf32(sw->m_w2[(8 * s + t) * 32 + 8 * N + q]);
                Bm[s][1] = tf32(sw->m_w2[(8 * s + t + 4) * 32 + 8 * N + q]);
            }
            float bb0 = sw->m_b2[8 * N + 2 * t], bb1 = sw->m_b2[8 * N + 2 * t + 1];
#pragma unroll
            for (int T = 0; T < 2; T++) {
                float c0 = bb0, c1 = bb1, c2 = bb0, c3 = bb1;
#pragma unroll
                for (int s = 0; s < 4; s++)
                    mma8(c0, c1, c2, c3,
                         Am[T][s][0], Am[T][s][1], Am[T][s][2], Am[T][s][3],
                         Bm[s][0], Bm[s][1]);
                h2p[T][N][0] = f2pack(lrelu(c0), lrelu(c1));
                h2p[T][N][1] = f2pack(lrelu(c2), lrelu(c3));
            }
        }
    }

    // ============== m3: 32 -> 2 (fp32, quad reduce) ==============
    {
        u64 w3p[4][2];
#pragma unroll
        for (int N = 0; N < 4; N++) {
            const int k = 8 * N + 2 * t;
            w3p[N][0] = *reinterpret_cast<const u64*>(sw->m_w3 + 2 * k);
            w3p[N][1] = *reinterpret_cast<const u64*>(sw->m_w3 + 2 * (k + 1));
        }
        const u64 bias = *reinterpret_cast<const u64*>(sw->m_b3);
#pragma unroll
        for (int T = 0; T < 2; T++)
#pragma unroll
            for (int b = 0; b < 2; b++) {
                u64 acc = 0ull;
#pragma unroll
                for (int N = 0; N < 4; N++) {
                    float ha, hb; f2unpack(h2p[T][N][b], ha, hb);
                    acc = f2fma(f2splat(ha), w3p[N][0], acc);
                    acc = f2fma(f2splat(hb), w3p[N][1], acc);
                }
                acc = f2add(acc, sh1(acc));
                acc = f2add(acc, sh2(acc));
                if (t == 0) {
                    acc = f2add(acc, bias);
                    float a, c; f2unpack(acc, a, c);
                    const int row = blockIdx.x * ROWS + rbase + 16 * T + q + 8 * b;
                    if (row < B)
                        reinterpret_cast<float2*>(out)[row] =
                            make_float2(tanhf(a), tanhf(c));
                }
            }
    }
}

extern "C" void kernel_launch(void* const* d_in, const int* in_sizes, int n_in,
                              void* d_out, int out_size) {
    const float* s_in = (const float*)d_in[0];
    const int B = in_sizes[0] / OBS;
    const size_t shbytes = (size_t)ROWS * OBS * sizeof(float) + sizeof(SW);
    cudaFuncSetAttribute(actor_kernel,
                         cudaFuncAttributeMaxDynamicSharedMemorySize, (int)shbytes);
    dim3 grid((B + ROWS - 1) / ROWS), block(NT);
    actor_kernel<<<grid, block, shbytes>>>(
        s_in,
        (const float*)d_in[1],  (const float*)d_in[2],
        (const float*)d_in[3],  (const float*)d_in[4],
        (const float*)d_in[5],  (const float*)d_in[6],
        (const float*)d_in[7],  (const float*)d_in[8],
        (const float*)d_in[9],  (const float*)d_in[10],
        (const float*)d_in[11], (const float*)d_in[12],
        (const float*)d_in[13], (const float*)d_in[14],
        (const float*)d_in[15], (const float*)d_in[16],
        (const float*)d_in[17], (const float*)d_in[18],
        (const float*)d_in[19], (const float*)d_in[20],
        (const float*)d_in[21], (const float*)d_in[22],
        (float*)d_out, B);
}

// round 14
// speedup vs baseline: 4.7842x; 1.0827x over previous
#include <cuda_runtime.h>
#include <stdint.h>
#include <math.h>

// ============================================================================
// Actor_att1 — R13: tf32 mma.sync (as R12) + activation-cvt elimination
// (raw fp32 bits into tf32 mma = truncation; weights stay cvt.rna) and
// 12-warp occupancy (NT=384, ROWS=384, 209KB smem).
// ============================================================================

typedef unsigned long long u64;
#define DINL __device__ __forceinline__

DINL u64 f2pack(float lo, float hi){u64 d;asm("mov.b64 %0,{%1,%2};":"=l"(d):"f"(lo),"f"(hi));return d;}
DINL u64 f2splat(float v){u64 d;asm("mov.b64 %0,{%1,%1};":"=l"(d):"f"(v));return d;}
DINL void f2unpack(u64 v,float&lo,float&hi){asm("mov.b64 {%0,%1},%2;":"=f"(lo),"=f"(hi):"l"(v));}
DINL u64 f2fma(u64 a,u64 b,u64 c){u64 d;asm("fma.rn.f32x2 %0,%1,%2,%3;":"=l"(d):"l"(a),"l"(b),"l"(c));return d;}
DINL u64 f2mul(u64 a,u64 b){u64 d;asm("mul.rn.f32x2 %0,%1,%2;":"=l"(d):"l"(a),"l"(b));return d;}
DINL u64 f2add(u64 a,u64 b){u64 d;asm("add.rn.f32x2 %0,%1,%2;":"=l"(d):"l"(a),"l"(b));return d;}
DINL u64 sh1(u64 v){return __shfl_xor_sync(0xffffffffu,v,1);}
DINL u64 sh2(u64 v){return __shfl_xor_sync(0xffffffffu,v,2);}
DINL float sf1(float v){return __shfl_xor_sync(0xffffffffu,v,1);}
DINL float sf2(float v){return __shfl_xor_sync(0xffffffffu,v,2);}

// weights: proper round-to-nearest tf32 (cold path)
DINL uint32_t tf32w(float x){uint32_t u;asm("cvt.rna.tf32.f32 %0,%1;":"=r"(u):"f"(x));return u;}
// activations: raw fp32 bits (HW uses top 19 bits -> truncation; hot path, free)
DINL uint32_t tf32a(float x){return __float_as_uint(x);}

DINL void mma8(float&c0,float&c1,float&c2,float&c3,
               uint32_t a0,uint32_t a1,uint32_t a2,uint32_t a3,
               uint32_t b0,uint32_t b1){
    asm("mma.sync.aligned.m16n8k8.row.col.f32.tf32.tf32.f32 "
        "{%0,%1,%2,%3},{%4,%5,%6,%7},{%8,%9},{%0,%1,%2,%3};"
        : "+f"(c0),"+f"(c1),"+f"(c2),"+f"(c3)
        : "r"(a0),"r"(a1),"r"(a2),"r"(a3),"r"(b0),"r"(b1));
}

DINL float lrelu(float x){ return fmaxf(x, 0.01f * x); }

#define NT 384
#define ROWS 384
#define OBS 127

struct SW {
    float en_w1[4 * 32];  float en_b1[32];  float en_w2[32 * 16]; float en_b2[16];
    float oa_w1[5 * 32];  float oa_b1[32];  float oa_w2[32 * 16]; float oa_b2[16];
    float oa_g[16];       float oa_bln[16];
    float g_w1[3 * 32];   float g_b1[32];   float g_w2[32 * 16];  float g_b2[16];
    float g_g[16];        float g_bln[16];
    float m_w1[48 * 32];  float m_b1[32];   float m_w2[32 * 32];  float m_b2[32];
    float m_w3[32 * 2];   float m_b3[16];
};

DINL void cp_smem(float* dst, const float* __restrict__ src, int n, int tid) {
    for (int i = tid; i < n; i += NT) dst[i] = src[i];
}

// Shared encoder: fp32 layer1 (K->32, dims t+4j) + tf32 mma layer2 (32->16).
template<int K>
DINL void enc(const float (&in)[2][2][K], const float (&w1v)[K * 8],
              const float (&b1v)[8], const uint32_t (&Bf)[2][4][2],
              const float (&b2v)[2][2], u64 (&ep)[2][2][2]) {
    uint32_t Alo[2][8], Ahi[2][8];
#pragma unroll
    for (int T = 0; T < 2; T++) {
        u64 acc[8];
#pragma unroll
        for (int j = 0; j < 8; j++) acc[j] = f2splat(b1v[j]);
#pragma unroll
        for (int k = 0; k < K; k++) {
            u64 xp = f2pack(in[T][0][k], in[T][1][k]);
#pragma unroll
            for (int j = 0; j < 8; j++)
                acc[j] = f2fma(xp, f2splat(w1v[k * 8 + j]), acc[j]);
        }
#pragma unroll
        for (int j = 0; j < 8; j++) {
            float a, b; f2unpack(acc[j], a, b);
            Alo[T][j] = tf32a(fmaxf(a, 0.f));
            Ahi[T][j] = tf32a(fmaxf(b, 0.f));
        }
    }
#pragma unroll
    for (int T = 0; T < 2; T++)
#pragma unroll
        for (int N = 0; N < 2; N++) {
            float c0 = b2v[N][0], c1 = b2v[N][1], c2 = b2v[N][0], c3 = b2v[N][1];
#pragma unroll
            for (int s = 0; s < 4; s++)
                mma8(c0, c1, c2, c3,
                     Alo[T][2 * s], Ahi[T][2 * s], Alo[T][2 * s + 1], Ahi[T][2 * s + 1],
                     Bf[N][s][0], Bf[N][s][1]);
            ep[T][N][0] = f2pack(fmaxf(c0, 0.f), fmaxf(c1, 0.f));
            ep[T][N][1] = f2pack(fmaxf(c2, 0.f), fmaxf(c3, 0.f));
        }
}

__global__ void __launch_bounds__(NT, 1)
actor_kernel(const float* __restrict__ s_in,
             const float* __restrict__ en_w1, const float* __restrict__ en_b1,
             const float* __restrict__ en_w2, const float* __restrict__ en_b2,
             const float* __restrict__ oa_w1, const float* __restrict__ oa_b1,
             const float* __restrict__ oa_w2, const float* __restrict__ oa_b2,
             const float* __restrict__ oa_g,  const float* __restrict__ oa_bln,
             const float* __restrict__ g_w1,  const float* __restrict__ g_b1,
             const float* __restrict__ g_w2,  const float* __restrict__ g_b2,
             const float* __restrict__ g_g,   const float* __restrict__ g_bln,
             const float* __restrict__ m_w1,  const float* __restrict__ m_b1,
             const float* __restrict__ m_w2,  const float* __restrict__ m_b2,
             const float* __restrict__ m_w3,  const float* __restrict__ m_b3,
             float* __restrict__ out, int B)
{
    extern __shared__ __align__(16) float smem[];
    float* xs = smem;                              // ROWS*OBS floats
    SW* sw = reinterpret_cast<SW*>(xs + ROWS * OBS);

    const int tid = threadIdx.x;

    // ---- coalesced input staging (tail zero-filled) ----
    {
        const size_t base = (size_t)blockIdx.x * ROWS * OBS;
        const size_t tot = (size_t)B * OBS;
        const float4* src4 = reinterpret_cast<const float4*>(s_in + base);
        float4* dst4 = reinterpret_cast<float4*>(xs);
        const int full4 = ROWS * OBS / 4;
        int n4 = full4;
        if (base + (size_t)full4 * 4 > tot) n4 = (int)((tot - base) / 4);
        for (int i = tid; i < n4; i += NT) dst4[i] = src4[i];
        if (n4 < full4) {
            float4 z = make_float4(0.f, 0.f, 0.f, 0.f);
            for (int i = n4 + tid; i < full4; i += NT) dst4[i] = z;
        }
    }

    cp_smem(sw->en_w1, en_w1, 4 * 32, tid);
    cp_smem(sw->en_b1, en_b1, 32, tid);
    cp_smem(sw->en_w2, en_w2, 32 * 16, tid);
    cp_smem(sw->en_b2, en_b2, 16, tid);
    cp_smem(sw->oa_w1, oa_w1, 5 * 32, tid);
    cp_smem(sw->oa_b1, oa_b1, 32, tid);
    cp_smem(sw->oa_w2, oa_w2, 32 * 16, tid);
    cp_smem(sw->oa_b2, oa_b2, 16, tid);
    cp_smem(sw->oa_g, oa_g, 16, tid);
    cp_smem(sw->oa_bln, oa_bln, 16, tid);
    cp_smem(sw->g_w1, g_w1, 3 * 32, tid);
    cp_smem(sw->g_b1, g_b1, 32, tid);
    cp_smem(sw->g_w2, g_w2, 32 * 16, tid);
    cp_smem(sw->g_b2, g_b2, 16, tid);
    cp_smem(sw->g_g, g_g, 16, tid);
    cp_smem(sw->g_bln, g_bln, 16, tid);
    cp_smem(sw->m_w1, m_w1, 48 * 32, tid);
    cp_smem(sw->m_b1, m_b1, 32, tid);
    cp_smem(sw->m_w2, m_w2, 32 * 32, tid);
    cp_smem(sw->m_b2, m_b2, 32, tid);
    cp_smem(sw->m_w3, m_w3, 32 * 2, tid);
    if (tid < 2) sw->m_b3[tid] = m_b3[tid];
    __syncthreads();

    const int warp = tid >> 5;
    const int lane = tid & 31;
    const int q = lane >> 2;          // item-group 0..7
    const int t = lane & 3;           // role 0..3
    const int rbase = warp * 32;      // CTA-local row base for this warp

    const float* xr[2][2];
#pragma unroll
    for (int T = 0; T < 2; T++)
#pragma unroll
        for (int b = 0; b < 2; b++)
            xr[T][b] = xs + (rbase + 16 * T + q + 8 * b) * OBS;

    // ================= self encoder: 4 -> 32 -> 16 =================
    u64 spv[2][2][2];
    {
        float w1v[32], b1v[8];
#pragma unroll
        for (int k = 0; k < 4; k++)
#pragma unroll
            for (int j = 0; j < 8; j++) w1v[k * 8 + j] = sw->en_w1[k * 32 + t + 4 * j];
#pragma unroll
        for (int j = 0; j < 8; j++) b1v[j] = sw->en_b1[t + 4 * j];
        uint32_t Bf[2][4][2];
        float b2v[2][2];
#pragma unroll
        for (int N = 0; N < 2; N++) {
#pragma unroll
            for (int s = 0; s < 4; s++) {
                Bf[N][s][0] = tf32w(sw->en_w2[(8 * s + t) * 16 + 8 * N + q]);
                Bf[N][s][1] = tf32w(sw->en_w2[(8 * s + t + 4) * 16 + 8 * N + q]);
            }
            b2v[N][0] = sw->en_b2[8 * N + 2 * t];
            b2v[N][1] = sw->en_b2[8 * N + 2 * t + 1];
        }
        float in[2][2][4];
#pragma unroll
        for (int T = 0; T < 2; T++)
#pragma unroll
            for (int b = 0; b < 2; b++)
#pragma unroll
                for (int k = 0; k < 4; k++) in[T][b][k] = xr[T][b][k];
        enc<4>(in, w1v, b1v, Bf, b2v, spv);
    }

    u64 ov[2][2][2], fv[2][2][2];

    // ================= other-agent attention: 15 entities, K=5 =================
    {
        float w1v[40], b1v[8];
#pragma unroll
        for (int k = 0; k < 5; k++)
#pragma unroll
            for (int j = 0; j < 8; j++) w1v[k * 8 + j] = sw->oa_w1[k * 32 + t + 4 * j];
#pragma unroll
        for (int j = 0; j < 8; j++) b1v[j] = sw->oa_b1[t + 4 * j];
        uint32_t Bf[2][4][2];
        float b2v[2][2];
#pragma unroll
        for (int N = 0; N < 2; N++) {
#pragma unroll
            for (int s = 0; s < 4; s++) {
                Bf[N][s][0] = tf32w(sw->oa_w2[(8 * s + t) * 16 + 8 * N + q]);
                Bf[N][s][1] = tf32w(sw->oa_w2[(8 * s + t + 4) * 16 + 8 * N + q]);
            }
            b2v[N][0] = sw->oa_b2[8 * N + 2 * t];
            b2v[N][1] = sw->oa_b2[8 * N + 2 * t + 1];
        }

        float mm[2][2], ll[2][2];
        u64 at[2][2][2];
#pragma unroll
        for (int T = 0; T < 2; T++)
#pragma unroll
            for (int b = 0; b < 2; b++) {
                mm[T][b] = -__int_as_float(0x7f800000);
                ll[T][b] = 0.f;
                at[T][0][b] = 0ull; at[T][1][b] = 0ull;
            }

#pragma unroll 1
        for (int i = 0; i < 15; i++) {
            float in[2][2][5];
#pragma unroll
            for (int T = 0; T < 2; T++)
#pragma unroll
                for (int b = 0; b < 2; b++) {
                    const float* xp = xr[T][b];
                    in[T][b][0] = xp[4 + 2 * i];
                    in[T][b][1] = xp[5 + 2 * i];
                    in[T][b][2] = xp[34 + 2 * i];
                    in[T][b][3] = xp[35 + 2 * i];
                    in[T][b][4] = xp[64 + i];
                }
            u64 ep[2][2][2];
            enc<5>(in, w1v, b1v, Bf, b2v, ep);

#pragma unroll
            for (int T = 0; T < 2; T++)
#pragma unroll
                for (int b = 0; b < 2; b++) {
                    u64 d = f2mul(spv[T][0][b], ep[T][0][b]);
                    d = f2fma(spv[T][1][b], ep[T][1][b], d);
                    float lo, hi; f2unpack(d, lo, hi);
                    float p = lo + hi;
                    p += sf1(p); p += sf2(p);
                    float s = p * 0.25f;
                    float nm = fmaxf(mm[T][b], s);
                    float corr = __expf(mm[T][b] - nm);
                    float pw   = __expf(s - nm);
                    mm[T][b] = nm;
                    ll[T][b] = ll[T][b] * corr + pw;
                    u64 cs = f2splat(corr), ps = f2splat(pw);
                    at[T][0][b] = f2fma(cs, at[T][0][b], f2mul(ps, ep[T][0][b]));
                    at[T][1][b] = f2fma(cs, at[T][1][b], f2mul(ps, ep[T][1][b]));
                }
        }

        float g4[4], bt4[4];
        g4[0] = sw->oa_g[2 * t];     g4[1] = sw->oa_g[2 * t + 1];
        g4[2] = sw->oa_g[8 + 2 * t]; g4[3] = sw->oa_g[8 + 2 * t + 1];
        bt4[0] = sw->oa_bln[2 * t];     bt4[1] = sw->oa_bln[2 * t + 1];
        bt4[2] = sw->oa_bln[8 + 2 * t]; bt4[3] = sw->oa_bln[8 + 2 * t + 1];
#pragma unroll
        for (int T = 0; T < 2; T++)
#pragma unroll
            for (int b = 0; b < 2; b++) {
                float inv = __fdividef(1.f, ll[T][b]);
                float v0, v1, v2, v3;
                f2unpack(at[T][0][b], v0, v1);
                f2unpack(at[T][1][b], v2, v3);
                v0 *= inv; v1 *= inv; v2 *= inv; v3 *= inv;
                float sm = v0 + v1 + v2 + v3;
                sm += sf1(sm); sm += sf2(sm);
                float mu = sm * (1.f / 16.f);
                float c0 = v0 - mu, c1 = v1 - mu, c2 = v2 - mu, c3 = v3 - mu;
                float vr = c0 * c0 + c1 * c1 + c2 * c2 + c3 * c3;
                vr += sf1(vr); vr += sf2(vr);
                float rs = rsqrtf(vr * (1.f / 16.f) + 1e-5f);
                ov[T][0][b] = f2pack(fmaxf(c0 * rs * g4[0] + bt4[0], 0.f),
                                     fmaxf(c1 * rs * g4[1] + bt4[1], 0.f));
                ov[T][1][b] = f2pack(fmaxf(c2 * rs * g4[2] + bt4[2], 0.f),
                                     fmaxf(c3 * rs * g4[3] + bt4[3], 0.f));
            }
    }

    // ================= food attention: 16 entities, K=3 =================
    {
        float w1v[24], b1v[8];
#pragma unroll
        for (int k = 0; k < 3; k++)
#pragma unroll
            for (int j = 0; j < 8; j++) w1v[k * 8 + j] = sw->g_w1[k * 32 + t + 4 * j];
#pragma unroll
        for (int j = 0; j < 8; j++) b1v[j] = sw->g_b1[t + 4 * j];
        uint32_t Bf[2][4][2];
        float b2v[2][2];
#pragma unroll
        for (int N = 0; N < 2; N++) {
#pragma unroll
            for (int s = 0; s < 4; s++) {
                Bf[N][s][0] = tf32w(sw->g_w2[(8 * s + t) * 16 + 8 * N + q]);
                Bf[N][s][1] = tf32w(sw->g_w2[(8 * s + t + 4) * 16 + 8 * N + q]);
            }
            b2v[N][0] = sw->g_b2[8 * N + 2 * t];
            b2v[N][1] = sw->g_b2[8 * N + 2 * t + 1];
        }

        float mm[2][2], ll[2][2];
        u64 at[2][2][2];
#pragma unroll
        for (int T = 0; T < 2; T++)
#pragma unroll
            for (int b = 0; b < 2; b++) {
                mm[T][b] = -__int_as_float(0x7f800000);
                ll[T][b] = 0.f;
                at[T][0][b] = 0ull; at[T][1][b] = 0ull;
            }

#pragma unroll 1
        for (int i = 0; i < 16; i++) {
            float in[2][2][3];
#pragma unroll
            for (int T = 0; T < 2; T++)
#pragma unroll
                for (int b = 0; b < 2; b++) {
                    const float* xp = xr[T][b];
                    in[T][b][0] = xp[79 + 3 * i];
                    in[T][b][1] = xp[80 + 3 * i];
                    in[T][b][2] = xp[81 + 3 * i];
                }
            u64 ep[2][2][2];
            enc<3>(in, w1v, b1v, Bf, b2v, ep);

#pragma unroll
            for (int T = 0; T < 2; T++)
#pragma unroll
                for (int b = 0; b < 2; b++) {
                    u64 d = f2mul(spv[T][0][b], ep[T][0][b]);
                    d = f2fma(spv[T][1][b], ep[T][1][b], d);
                    float lo, hi; f2unpack(d, lo, hi);
                    float p = lo + hi;
                    p += sf1(p); p += sf2(p);
                    float s = p * 0.25f;
                    float nm = fmaxf(mm[T][b], s);
                    float corr = __expf(mm[T][b] - nm);
                    float pw   = __expf(s - nm);
                    mm[T][b] = nm;
                    ll[T][b] = ll[T][b] * corr + pw;
                    u64 cs = f2splat(corr), ps = f2splat(pw);
                    at[T][0][b] = f2fma(cs, at[T][0][b], f2mul(ps, ep[T][0][b]));
                    at[T][1][b] = f2fma(cs, at[T][1][b], f2mul(ps, ep[T][1][b]));
                }
        }

        float g4[4], bt4[4];
        g4[0] = sw->g_g[2 * t];     g4[1] = sw->g_g[2 * t + 1];
        g4[2] = sw->g_g[8 + 2 * t]; g4[3] = sw->g_g[8 + 2 * t + 1];
        bt4[0] = sw->g_bln[2 * t];     bt4[1] = sw->g_bln[2 * t + 1];
        bt4[2] = sw->g_bln[8 + 2 * t]; bt4[3] = sw->g_bln[8 + 2 * t + 1];
#pragma unroll
        for (int T = 0; T < 2; T++)
#pragma unroll
            for (int b = 0; b < 2; b++) {
                float inv = __fdividef(1.f, ll[T][b]);
                float v0, v1, v2, v3;
                f2unpack(at[T][0][b], v0, v1);
                f2unpack(at[T][1][b], v2, v3);
                v0 *= inv; v1 *= inv; v2 *= inv; v3 *= inv;
                float sm = v0 + v1 + v2 + v3;
                sm += sf1(sm); sm += sf2(sm);
                float mu = sm * (1.f / 16.f);
                float c0 = v0 - mu, c1 = v1 - mu, c2 = v2 - mu, c3 = v3 - mu;
                float vr = c0 * c0 + c1 * c1 + c2 * c2 + c3 * c3;
                vr += sf1(vr); vr += sf2(vr);
                float rs = rsqrtf(vr * (1.f / 16.f) + 1e-5f);
                fv[T][0][b] = f2pack(fmaxf(c0 * rs * g4[0] + bt4[0], 0.f),
                                     fmaxf(c1 * rs * g4[1] + bt4[1], 0.f));
                fv[T][1][b] = f2pack(fmaxf(c2 * rs * g4[2] + bt4[2], 0.f),
                                     fmaxf(c3 * rs * g4[3] + bt4[3], 0.f));
            }
    }

    // ============== merged vector -> smem (reuse this warp's x rows) ==============
#pragma unroll
    for (int T = 0; T < 2; T++)
#pragma unroll
        for (int b = 0; b < 2; b++) {
            float* M = xs + (rbase + 16 * T + q + 8 * b) * OBS;
#pragma unroll
            for (int N = 0; N < 2; N++) {
                float a, c;
                f2unpack(spv[T][N][b], a, c);
                M[8 * N + 2 * t] = a; M[8 * N + 2 * t + 1] = c;
                f2unpack(fv[T][N][b], a, c);
                M[16 + 8 * N + 2 * t] = a; M[16 + 8 * N + 2 * t + 1] = c;
                f2unpack(ov[T][N][b], a, c);
                M[32 + 8 * N + 2 * t] = a; M[32 + 8 * N + 2 * t + 1] = c;
            }
        }
    __syncwarp();

    // ============== m1: 48 -> 32 via mma (K=48, 6 k-steps) ==============
    {
        uint32_t Am[2][6][4];
#pragma unroll
        for (int T = 0; T < 2; T++) {
            const float* r0 = xs + (rbase + 16 * T + q) * OBS;
            const float* r1 = r0 + 8 * OBS;
#pragma unroll
            for (int s = 0; s < 6; s++) {
                Am[T][s][0] = tf32a(r0[8 * s + t]);
                Am[T][s][1] = tf32a(r1[8 * s + t]);
                Am[T][s][2] = tf32a(r0[8 * s + t + 4]);
                Am[T][s][3] = tf32a(r1[8 * s + t + 4]);
            }
        }
#pragma unroll
        for (int N = 0; N < 4; N++) {
            uint32_t Bm[6][2];
#pragma unroll
            for (int s = 0; s < 6; s++) {
                Bm[s][0] = tf32w(sw->m_w1[(8 * s + t) * 32 + 8 * N + q]);
                Bm[s][1] = tf32w(sw->m_w1[(8 * s + t + 4) * 32 + 8 * N + q]);
            }
            float bb0 = sw->m_b1[8 * N + 2 * t], bb1 = sw->m_b1[8 * N + 2 * t + 1];
#pragma unroll
            for (int T = 0; T < 2; T++) {
                float c0 = bb0, c1 = bb1, c2 = bb0, c3 = bb1;
#pragma unroll
                for (int s = 0; s < 6; s++)
                    mma8(c0, c1, c2, c3,
                         Am[T][s][0], Am[T][s][1], Am[T][s][2], Am[T][s][3],
                         Bm[s][0], Bm[s][1]);
                float* r0 = xs + (rbase + 16 * T + q) * OBS;
                float* r1 = r0 + 8 * OBS;
                r0[64 + 8 * N + 2 * t]     = lrelu(c0);
                r0[64 + 8 * N + 2 * t + 1] = lrelu(c1);
                r1[64 + 8 * N + 2 * t]     = lrelu(c2);
                r1[64 + 8 * N + 2 * t + 1] = lrelu(c3);
            }
        }
    }
    __syncwarp();

    // ============== m2: 32 -> 32 via mma (K=32, 4 k-steps) ==============
    u64 h2p[2][4][2];
    {
        uint32_t Am[2][4][4];
#pragma unroll
        for (int T = 0; T < 2; T++) {
            const float* r0 = xs + (rbase + 16 * T + q) * OBS;
            const float* r1 = r0 + 8 * OBS;
#pragma unroll
            for (int s = 0; s < 4; s++) {
                Am[T][s][0] = tf32a(r0[64 + 8 * s + t]);
                Am[T][s][1] = tf32a(r1[64 + 8 * s + t]);
                Am[T][s][2] = tf32a(r0[64 + 8 * s + t + 4]);
                Am[T][s][3] = tf32a(r1[64 + 8 * s + t + 4]);
            }
        }
#pragma unroll
        for (int N = 0; N < 4; N++) {
            uint32_t Bm[4][2];
#pragma unroll
            for (int s = 0; s < 4; s++) {
                Bm[s][0] = tf32w(sw->m_w2[(8 * s + t) * 32 + 8 * N + q]);
                Bm[s][1] = tf32w(sw->m_w2[(8 * s + t + 4) * 32 + 8 * N + q]);
            }
            float bb0 = sw->m_b2[8 * N + 2 * t], bb1 = sw->m_b2[8 * N + 2 * t + 1];
#pragma unroll
            for (int T = 0; T < 2; T++) {
                float c0 = bb0, c1 = bb1, c2 = bb0, c3 = bb1;
#pragma unroll
                for (int s = 0; s < 4; s++)
                    mma8(c0, c1, c2, c3,
                         Am[T][s][0], Am[T][s][1], Am[T][s][2], Am[T][s][3],
                         Bm[s][0], Bm[s][1]);
                h2p[T][N][0] = f2pack(lrelu(c0), lrelu(c1));
                h2p[T][N][1] = f2pack(lrelu(c2), lrelu(c3));
            }
        }
    }

    // ============== m3: 32 -> 2 (fp32, quad reduce) ==============
    {
        u64 w3p[4][2];
#pragma unroll
        for (int N = 0; N < 4; N++) {
            const int k = 8 * N + 2 * t;
            w3p[N][0] = *reinterpret_cast<const u64*>(sw->m_w3 + 2 * k);
            w3p[N][1] = *reinterpret_cast<const u64*>(sw->m_w3 + 2 * (k + 1));
        }
        const u64 bias = *reinterpret_cast<const u64*>(sw->m_b3);
#pragma unroll
        for (int T = 0; T < 2; T++)
#pragma unroll
            for (int b = 0; b < 2; b++) {
                u64 acc = 0ull;
#pragma unroll
                for (int N = 0; N < 4; N++) {
                    float ha, hb; f2unpack(h2p[T][N][b], ha, hb);
                    acc = f2fma(f2splat(ha), w3p[N][0], acc);
                    acc = f2fma(f2splat(hb), w3p[N][1], acc);
                }
                acc = f2add(acc, sh1(acc));
                acc = f2add(acc, sh2(acc));
                if (t == 0) {
                    acc = f2add(acc, bias);
                    float a, c; f2unpack(acc, a, c);
                    const int row = blockIdx.x * ROWS + rbase + 16 * T + q + 8 * b;
                    if (row < B)
                        reinterpret_cast<float2*>(out)[row] =
                            make_float2(tanhf(a), tanhf(c));
                }
            }
    }
}

extern "C" void kernel_launch(void* const* d_in, const int* in_sizes, int n_in,
                              void* d_out, int out_size) {
    const float* s_in = (const float*)d_in[0];
    const int B = in_sizes[0] / OBS;
    const size_t shbytes = (size_t)ROWS * OBS * sizeof(float) + sizeof(SW);
    cudaFuncSetAttribute(actor_kernel,
                         cudaFuncAttributeMaxDynamicSharedMemorySize, (int)shbytes);
    dim3 grid((B + ROWS - 1) / ROWS), block(NT);
    actor_kernel<<<grid, block, shbytes>>>(
        s_in,
        (const float*)d_in[1],  (const float*)d_in[2],
        (const float*)d_in[3],  (const float*)d_in[4],
        (const float*)d_in[5],  (const float*)d_in[6],
        (const float*)d_in[7],  (const float*)d_in[8],
        (const float*)d_in[9],  (const float*)d_in[10],
        (const float*)d_in[11], (const float*)d_in[12],
        (const float*)d_in[13], (const float*)d_in[14],
        (const float*)d_in[15], (const float*)d_in[16],
        (const float*)d_in[17], (const float*)d_in[18],
        (const float*)d_in[19], (const float*)d_in[20],
        (const float*)d_in[21], (const float*)d_in[22],
        (float*)d_out, B);
}